// round 7
// baseline (speedup 1.0000x reference)
#include <cuda_runtime.h>
#include <cuda_bf16.h>
#include <cstdint>

#define BATCH 8
#define SEQ   2048
#define DM    1024
#define ED    64

// ---------------- device scratch (allocation-free rule) ----------------
__device__ __nv_bfloat16 g_qh[BATCH*SEQ*ED], g_ql[BATCH*SEQ*ED];
__device__ __nv_bfloat16 g_kh[BATCH*SEQ*ED], g_kl[BATCH*SEQ*ED];
__device__ __nv_bfloat16 g_vth[BATCH*ED*SEQ], g_vtl[BATCH*ED*SEQ];   // V transposed [b][e][t]
__device__ __nv_bfloat16 g_wth[3*ED*DM],  g_wtl[3*ED*DM];            // W^T [mat][n][d]
// split-K partials: [b][qt][chunk][128][64] fp32 + per-row m/l
__device__ float g_pctx[BATCH*16*4*128*64];
__device__ float g_pm[BATCH*16*4*128];
__device__ float g_pl[BATCH*16*4*128];

// unit table: (qt<<2)|chunk, sorted by chunk size descending (8,6,4,2 tiles)
__constant__ uint8_t c_units[40] = {
    (3<<2)|0,(4<<2)|0,(5<<2)|0,(6<<2)|0,(7<<2)|0,(7<<2)|1,(8<<2)|0,(8<<2)|1,
    (9<<2)|0,(9<<2)|1,(10<<2)|0,(10<<2)|1,(11<<2)|0,(11<<2)|1,(11<<2)|2,
    (12<<2)|0,(12<<2)|1,(12<<2)|2,(13<<2)|0,(13<<2)|1,(13<<2)|2,
    (14<<2)|0,(14<<2)|1,(14<<2)|2,(15<<2)|0,(15<<2)|1,(15<<2)|2,(15<<2)|3,
    (2<<2)|0,(6<<2)|1,(10<<2)|2,(14<<2)|3,
    (1<<2)|0,(5<<2)|1,(9<<2)|2,(13<<2)|3,
    (0<<2)|0,(4<<2)|1,(8<<2)|2,(12<<2)|3
};

// ---------------- helpers ----------------
__device__ __forceinline__ uint32_t smem_u32(const void* p) {
    uint32_t a;
    asm("{ .reg .u64 t; cvta.to.shared.u64 t, %1; cvt.u32.u64 %0, t; }" : "=r"(a) : "l"(p));
    return a;
}
__device__ __forceinline__ void ldmA(uint32_t* a, uint32_t addr) {
    asm volatile("ldmatrix.sync.aligned.m8n8.x4.shared.b16 {%0,%1,%2,%3}, [%4];"
        : "=r"(a[0]), "=r"(a[1]), "=r"(a[2]), "=r"(a[3]) : "r"(addr));
}
__device__ __forceinline__ void ldmB(uint32_t* b, uint32_t addr) {
    asm volatile("ldmatrix.sync.aligned.m8n8.x2.shared.b16 {%0,%1}, [%2];"
        : "=r"(b[0]), "=r"(b[1]) : "r"(addr));
}
__device__ __forceinline__ void mmaf(float* d, const uint32_t* a, const uint32_t* b) {
    asm volatile("mma.sync.aligned.m16n8k16.row.col.f32.bf16.bf16.f32 "
        "{%0,%1,%2,%3}, {%4,%5,%6,%7}, {%8,%9}, {%0,%1,%2,%3};"
        : "+f"(d[0]), "+f"(d[1]), "+f"(d[2]), "+f"(d[3])
        : "r"(a[0]), "r"(a[1]), "r"(a[2]), "r"(a[3]), "r"(b[0]), "r"(b[1]));
}
#define CP16(dst, src)  asm volatile("cp.async.cg.shared.global [%0], [%1], 16;" :: "r"(dst), "l"(src) : "memory")
#define CP_COMMIT()     asm volatile("cp.async.commit_group;" ::: "memory")
#define CP_WAIT0()      asm volatile("cp.async.wait_group 0;" ::: "memory")
#define CP_WAIT1()      asm volatile("cp.async.wait_group 1;" ::: "memory")

union U4 { uint4 u; __nv_bfloat16 h[8]; };
union U2 { uint2 u; __nv_bfloat16 h[4]; };
union UB2 { uint32_t u; __nv_bfloat16 h[2]; };

__device__ __forceinline__ void split2(float f, __nv_bfloat16& hi, __nv_bfloat16& lo) {
    hi = __float2bfloat16(f);
    lo = __float2bfloat16(f - __bfloat162float(hi));
}
__device__ __forceinline__ uint32_t packbf(__nv_bfloat16 a, __nv_bfloat16 b) {
    UB2 u; u.h[0] = a; u.h[1] = b; return u.u;
}

// ---------------------------------------------------------------------------
// Kernel 0: weights -> transposed bf16 hi/lo.
// ---------------------------------------------------------------------------
__global__ void prep_kernel(const float* __restrict__ Wq, const float* __restrict__ Wk,
                            const float* __restrict__ Wv)
{
    int tid = blockIdx.x * 256 + threadIdx.x;
    for (int i = tid; i < 3 * ED * DM; i += 96 * 256) {
        int mat = i >> 16, rem = i & 65535;
        int n = rem >> 10, d = rem & 1023;
        const float* W = (mat == 0) ? Wq : (mat == 1) ? Wk : Wv;
        __nv_bfloat16 h, l;
        split2(W[d * ED + n], h, l);
        g_wth[i] = h; g_wtl[i] = l;
    }
}

// ---------------------------------------------------------------------------
// Kernel 1: QKV projection via mma.sync bf16x3 (W staged via cp.async).
// grid (128, 3) x 256 thr; launch_bounds(256,2) for 2-CTA occupancy.
// ---------------------------------------------------------------------------
#define PJ_XH 512
#define PJ_XL 18944
#define PJ_WH 37376
#define PJ_WL 46592
#define PJ_SMEM 55808

__global__ void __launch_bounds__(256, 2)
proj_kernel(const float* __restrict__ x, const float* __restrict__ bq,
            const float* __restrict__ bk, const float* __restrict__ bv)
{
    extern __shared__ char smem[];
    const uint32_t sb = smem_u32(smem);
    const int tid = threadIdx.x, lane = tid & 31, wid = tid >> 5;
    const int mw = wid >> 1, nh = wid & 1;
    const int g = lane >> 2, tq = lane & 3;
    const int mat = blockIdx.y;
    const int rowbase = blockIdx.x * 128;
    const float* bias = (mat == 0) ? bq : (mat == 1) ? bk : bv;
    if (tid < 64) ((float*)smem)[tid] = bias[tid];

    const __nv_bfloat16* wh = g_wth + (size_t)mat * ED * DM;
    const __nv_bfloat16* wl = g_wtl + (size_t)mat * ED * DM;

    float acc[2][4][4];
#pragma unroll
    for (int a = 0; a < 2; a++)
#pragma unroll
        for (int bb = 0; bb < 4; bb++)
#pragma unroll
            for (int c = 0; c < 4; c++) acc[a][bb][c] = 0.0f;

    for (int k0 = 0; k0 < DM; k0 += 64) {
        __syncthreads();
        // W tiles via cp.async, issued first so they overlap X conversion
#pragma unroll
        for (int i = 0; i < 4; i++) {
            int idx = i * 256 + tid;
            int part = idx >> 9, rem = idx & 511;
            int r = rem >> 3, jj = rem & 7;
            const __nv_bfloat16* src = (part ? wl : wh) + (size_t)r * DM + k0;
            CP16(sb + (part ? PJ_WL : PJ_WH) + r * 144 + jj * 16, (const char*)src + jj * 16);
        }
        CP_COMMIT();
#pragma unroll
        for (int i = 0; i < 8; i++) {                    // X tile 128x64 fp32 -> hi/lo
            int idx = i * 256 + tid;
            int r = idx >> 4, jj = idx & 15;
            float4 v = __ldg((const float4*)(x + (size_t)(rowbase + r) * DM + k0) + jj);
            U2 h, l;
            split2(v.x, h.h[0], l.h[0]); split2(v.y, h.h[1], l.h[1]);
            split2(v.z, h.h[2], l.h[2]); split2(v.w, h.h[3], l.h[3]);
            *(uint2*)(smem + PJ_XH + r * 144 + jj * 8) = h.u;
            *(uint2*)(smem + PJ_XL + r * 144 + jj * 8) = l.u;
        }
        CP_WAIT0();
        __syncthreads();

#pragma unroll
        for (int kc = 0; kc < 4; kc++) {
            uint32_t ah[2][4], al[2][4];
#pragma unroll
            for (int mi = 0; mi < 2; mi++) {
                uint32_t ao = (uint32_t)(mw * 32 + mi * 16 + (lane & 15)) * 144 + kc * 32 + (lane >> 4) * 16;
                ldmA(ah[mi], sb + PJ_XH + ao);
                ldmA(al[mi], sb + PJ_XL + ao);
            }
#pragma unroll
            for (int ni = 0; ni < 4; ni++) {
                uint32_t bo = (uint32_t)(nh * 32 + ni * 8 + (lane & 7)) * 144 + kc * 32 + ((lane >> 3) & 1) * 16;
                uint32_t bh[2], bl[2];
                ldmB(bh, sb + PJ_WH + bo);
                ldmB(bl, sb + PJ_WL + bo);
#pragma unroll
                for (int mi = 0; mi < 2; mi++) {
                    mmaf(acc[mi][ni], ah[mi], bh);
                    mmaf(acc[mi][ni], ah[mi], bl);
                    mmaf(acc[mi][ni], al[mi], bh);
                }
            }
        }
    }

    // epilogue: fragments -> staged smem [128][65] -> coalesced hi/lo global stores
    __syncthreads();
    const float scale = (mat == 0) ? 0.125f : 1.0f;
    const float* bs = (const float*)smem;
    float* stg = (float*)(smem + 512);
#pragma unroll
    for (int mi = 0; mi < 2; mi++)
#pragma unroll
        for (int ni = 0; ni < 4; ni++)
#pragma unroll
            for (int j = 0; j < 4; j++) {
                int row = mw * 32 + mi * 16 + (j >> 1) * 8 + g;
                int col = nh * 32 + ni * 8 + tq * 2 + (j & 1);
                stg[row * 65 + col] = (acc[mi][ni][j] + bs[col]) * scale;
            }
    __syncthreads();

    if (mat < 2) {
        int r = tid >> 1, half = tid & 1;
        U4 hb[4], lb[4];
#pragma unroll
        for (int i = 0; i < 32; i++)
            split2(stg[r * 65 + half * 32 + i], hb[i >> 3].h[i & 7], lb[i >> 3].h[i & 7]);
        __nv_bfloat16* dh = ((mat == 0) ? g_qh : g_kh) + (size_t)(rowbase + r) * ED + half * 32;
        __nv_bfloat16* dl = ((mat == 0) ? g_ql : g_kl) + (size_t)(rowbase + r) * ED + half * 32;
#pragma unroll
        for (int i = 0; i < 4; i++) { ((uint4*)dh)[i] = hb[i].u; ((uint4*)dl)[i] = lb[i].u; }
    } else {
        int e = tid >> 2, qq = tid & 3;
        int b = rowbase >> 11, tb = (rowbase & 2047) + qq * 32;
        U4 hb[4], lb[4];
#pragma unroll
        for (int i = 0; i < 32; i++)
            split2(stg[(qq * 32 + i) * 65 + e], hb[i >> 3].h[i & 7], lb[i >> 3].h[i & 7]);
        __nv_bfloat16* dh = g_vth + (size_t)(b * ED + e) * SEQ + tb;
        __nv_bfloat16* dl = g_vtl + (size_t)(b * ED + e) * SEQ + tb;
#pragma unroll
        for (int i = 0; i < 4; i++) { ((uint4*)dh)[i] = hb[i].u; ((uint4*)dl)[i] = lb[i].u; }
    }
}

// ---------------------------------------------------------------------------
// Kernel 2: split-K causal flash attention partials.
// 8 warps x 16 rows x full N=64 -> softmax is warp-local (shuffle only).
// grid (40, 8) x 256 thr. cp.async double-buffered K/V stages.
// SMEM: QH@2048 QL@20480 KV stages@38912 (2 x 36864). ctxb reuses Q area.
// ---------------------------------------------------------------------------
#define AT_QH   2048
#define AT_QL   20480
#define AT_ST   38912
#define AT_STG  36864
#define AT_CTXB 2048
#define AT_SMEM 112640

__global__ void __launch_bounds__(256, 1)
attn_partial(float* __restrict__ dummy)
{
    extern __shared__ char smem[];
    const uint32_t sb = smem_u32(smem);
    const int tid = threadIdx.x, lane = tid & 31, wid = tid >> 5;
    const int g = lane >> 2, tq = lane & 3;
    const int b = blockIdx.y;
    const uint32_t u = c_units[blockIdx.x];
    const int qt = u >> 2, ck = u & 3;
    const int qb = qt * 128;
    const int t0 = ck * 8;
    const int t1 = min(t0 + 8, 2 * qt + 2);

    // Q tile hi/lo via cp.async (group 0)
#pragma unroll
    for (int i = 0; i < 8; i++) {
        int idx = i * 256 + tid;
        int part = idx >> 10, rem = idx & 1023;
        int r = rem >> 3, jj = rem & 7;
        const __nv_bfloat16* src = (part ? g_ql : g_qh) + (size_t)(b * SEQ + qb + r) * ED;
        CP16(sb + (part ? AT_QL : AT_QH) + r * 144 + jj * 16, (const char*)src + jj * 16);
    }
    CP_COMMIT();

    auto stage_tile = [&](int t, int sg) {
        uint32_t base = sb + AT_ST + sg * AT_STG;
#pragma unroll
        for (int i = 0; i < 8; i++) {
            int idx = i * 256 + tid;
            int part = idx >> 9, rem = idx & 511;
            int r = rem >> 3, jj = rem & 7;
            const __nv_bfloat16* src;
            if (part == 0)      src = g_kh  + (size_t)(b * SEQ + t * 64 + r) * ED;
            else if (part == 1) src = g_kl  + (size_t)(b * SEQ + t * 64 + r) * ED;
            else if (part == 2) src = g_vth + (size_t)(b * ED + r) * SEQ + t * 64;
            else                src = g_vtl + (size_t)(b * ED + r) * SEQ + t * 64;
            CP16(base + part * 9216 + r * 144 + jj * 16, (const char*)src + jj * 16);
        }
    };
    stage_tile(t0, 0);
    CP_COMMIT();

    float ctx[8][4];
#pragma unroll
    for (int bb = 0; bb < 8; bb++)
#pragma unroll
        for (int c = 0; c < 4; c++) ctx[bb][c] = 0.0f;
    float mrow[2] = {-1e30f, -1e30f};
    float lrow[2] = {0.0f, 0.0f};

    for (int t = t0; t < t1; t++) {
        const int cur = (t - t0) & 1;
        __syncthreads();             // all warps done reading stage cur^1 (iter t-1)
        if (t + 1 < t1) { stage_tile(t + 1, cur ^ 1); CP_COMMIT(); CP_WAIT1(); }
        else            { CP_WAIT0(); }
        __syncthreads();             // stage cur visible to all warps
        const uint32_t kb = sb + AT_ST + cur * AT_STG;

        // S = Q K^T : warp's 16 rows x full 64 keys
        float s[8][4];
#pragma unroll
        for (int bb = 0; bb < 8; bb++)
#pragma unroll
            for (int c = 0; c < 4; c++) s[bb][c] = 0.0f;

#pragma unroll
        for (int kc = 0; kc < 4; kc++) {
            uint32_t ah[4], al[4];
            uint32_t ao = (uint32_t)(wid * 16 + (lane & 15)) * 144 + kc * 32 + (lane >> 4) * 16;
            ldmA(ah, sb + AT_QH + ao);
            ldmA(al, sb + AT_QL + ao);
#pragma unroll
            for (int ni = 0; ni < 8; ni++) {
                uint32_t bo = (uint32_t)(ni * 8 + (lane & 7)) * 144 + kc * 32 + ((lane >> 3) & 1) * 16;
                uint32_t bh[2], bl[2];
                ldmB(bh, kb + bo);
                ldmB(bl, kb + 9216 + bo);
                mmaf(s[ni], ah, bh);
                mmaf(s[ni], ah, bl);
                mmaf(s[ni], al, bh);
            }
        }

        if (t >= 2 * qt) {                               // causal mask (diagonal tiles)
#pragma unroll
            for (int ni = 0; ni < 8; ni++)
#pragma unroll
                for (int j = 0; j < 4; j++) {
                    int row = qb + wid * 16 + (j >> 1) * 8 + g;
                    int col = t * 64 + ni * 8 + tq * 2 + (j & 1);
                    if (col > row) s[ni][j] = -1e30f;
                }
        }

        // warp-local online softmax (quad shuffle only)
        float corr[2];
#pragma unroll
        for (int rh = 0; rh < 2; rh++) {
            float mx = -1e30f;
#pragma unroll
            for (int ni = 0; ni < 8; ni++)
                mx = fmaxf(mx, fmaxf(s[ni][rh * 2], s[ni][rh * 2 + 1]));
            mx = fmaxf(mx, __shfl_xor_sync(0xffffffffu, mx, 1));
            mx = fmaxf(mx, __shfl_xor_sync(0xffffffffu, mx, 2));
            float nm = fmaxf(mrow[rh], mx);
            corr[rh] = __expf(mrow[rh] - nm);
            mrow[rh] = nm;
            float sum = 0.0f;
#pragma unroll
            for (int ni = 0; ni < 8; ni++) {
                float p0 = __expf(s[ni][rh * 2] - nm);
                float p1 = __expf(s[ni][rh * 2 + 1] - nm);
                s[ni][rh * 2] = p0; s[ni][rh * 2 + 1] = p1;
                sum += p0 + p1;
            }
            sum += __shfl_xor_sync(0xffffffffu, sum, 1);
            sum += __shfl_xor_sync(0xffffffffu, sum, 2);
            lrow[rh] = lrow[rh] * corr[rh] + sum;
        }
#pragma unroll
        for (int ni = 0; ni < 8; ni++)
#pragma unroll
            for (int j = 0; j < 4; j++) ctx[ni][j] *= corr[j >> 1];

        // PV: P (regs, hi/lo A-frags) @ V^T (smem B-frags)
#pragma unroll
        for (int kc = 0; kc < 4; kc++) {
            uint32_t ph[4], pl[4];
            {
                __nv_bfloat16 h0, l0, h1, l1;
                split2(s[2 * kc][0], h0, l0);     split2(s[2 * kc][1], h1, l1);
                ph[0] = packbf(h0, h1);           pl[0] = packbf(l0, l1);
                split2(s[2 * kc][2], h0, l0);     split2(s[2 * kc][3], h1, l1);
                ph[1] = packbf(h0, h1);           pl[1] = packbf(l0, l1);
                split2(s[2 * kc + 1][0], h0, l0); split2(s[2 * kc + 1][1], h1, l1);
                ph[2] = packbf(h0, h1);           pl[2] = packbf(l0, l1);
                split2(s[2 * kc + 1][2], h0, l0); split2(s[2 * kc + 1][3], h1, l1);
                ph[3] = packbf(h0, h1);           pl[3] = packbf(l0, l1);
            }
#pragma unroll
            for (int ni = 0; ni < 8; ni++) {
                uint32_t bo = (uint32_t)(ni * 8 + (lane & 7)) * 144 + kc * 32 + ((lane >> 3) & 1) * 16;
                uint32_t bh[2], bl[2];
                ldmB(bh, kb + 18432 + bo);
                ldmB(bl, kb + 27648 + bo);
                mmaf(ctx[ni], ph, bh);
                mmaf(ctx[ni], ph, bl);
                mmaf(ctx[ni], pl, bh);
            }
        }
    }

    // ---- write partials (unnormalized ctx + m/l) ----
    __syncthreads();                 // Q area dead; safe to reuse as ctxb
    float* ctxb = (float*)(smem + AT_CTXB);    // stride 68 floats
#pragma unroll
    for (int ni = 0; ni < 8; ni++)
#pragma unroll
        for (int j = 0; j < 4; j++) {
            int row = wid * 16 + (j >> 1) * 8 + g;
            int col = ni * 8 + tq * 2 + (j & 1);
            ctxb[row * 68 + col] = ctx[ni][j];
        }
    if (tq == 0) {
        size_t mlb = (size_t)((b * 16 + qt) * 4 + ck) * 128;
#pragma unroll
        for (int rh = 0; rh < 2; rh++) {
            int row = wid * 16 + rh * 8 + g;
            g_pm[mlb + row] = mrow[rh];
            g_pl[mlb + row] = lrow[rh];
        }
    }
    __syncthreads();

    const int r = tid >> 1, half = tid & 1;
    float* dst = g_pctx + ((size_t)((b * 16 + qt) * 4 + ck) << 13) + r * 64 + half * 32;
    const float4* srcf = (const float4*)(ctxb + r * 68 + half * 32);
#pragma unroll
    for (int i = 0; i < 8; i++) ((float4*)dst)[i] = srcf[i];
    (void)dummy;
}

// ---------------------------------------------------------------------------
// Kernel 3: combine partials + output projection. grid (64, 8) x 256 thr.
// Each CTA: 32 rows. SMEM: ctxs[32][65]f32 @0, W0 @8448, b0 @24832. 25088 B.
// ---------------------------------------------------------------------------
#define CB_W0 8448
#define CB_B0 24832
#define CB_SMEM 25088

__global__ void __launch_bounds__(256, 1)
combine_kernel(const float* __restrict__ W0, const float* __restrict__ b0,
               float* __restrict__ out)
{
    extern __shared__ char smem[];
    const int tid = threadIdx.x;
    const int qt = blockIdx.x >> 2, sub = blockIdx.x & 3, b = blockIdx.y;
    const int rowb = sub * 32;
    const int nchunks = (qt >> 2) + 1;

#pragma unroll
    for (int i = 0; i < 4; i++)
        ((float4*)(smem + CB_W0))[i * 256 + tid] = __ldg((const float4*)W0 + i * 256 + tid);
    if (tid < 64) ((float*)(smem + CB_B0))[tid] = b0[tid];

    // combine chunk partials for this thread's (row, 8-col block)
    const int r = tid >> 3, eb = tid & 7;     // r: 0..31, eb: 0..7
    const int row = rowb + r;
    const size_t base = (size_t)((b * 16 + qt) * 4);
    float mc[4], lc[4];
#pragma unroll
    for (int c = 0; c < 4; c++) {
        if (c < nchunks) {
            mc[c] = g_pm[(base + c) * 128 + row];
            lc[c] = g_pl[(base + c) * 128 + row];
        } else { mc[c] = -1e30f; lc[c] = 0.0f; }
    }
    float ms = fmaxf(fmaxf(mc[0], mc[1]), fmaxf(mc[2], mc[3]));
    float ls = 0.0f, wsc[4];
#pragma unroll
    for (int c = 0; c < 4; c++) { wsc[c] = __expf(mc[c] - ms); ls += lc[c] * wsc[c]; }
    const float inv = 1.0f / ls;

    float acc[8];
#pragma unroll
    for (int i = 0; i < 8; i++) acc[i] = 0.0f;
#pragma unroll
    for (int c = 0; c < 4; c++) {
        if (c < nchunks) {
            const float4* p = (const float4*)(g_pctx + ((base + c) << 13) + row * 64 + eb * 8);
            float w = wsc[c];
            float4 v0 = p[0], v1 = p[1];
            acc[0] += v0.x * w; acc[1] += v0.y * w; acc[2] += v0.z * w; acc[3] += v0.w * w;
            acc[4] += v1.x * w; acc[5] += v1.y * w; acc[6] += v1.z * w; acc[7] += v1.w * w;
        }
    }
    float* ctxs = (float*)smem;
#pragma unroll
    for (int i = 0; i < 8; i++) ctxs[r * 65 + eb * 8 + i] = acc[i] * inv;
    __syncthreads();

    // out[row] = ctx[row] @ W0 + b0 ; thread handles 8 outputs
    const float* b0s = (const float*)(smem + CB_B0);
    const float* w0s = (const float*)(smem + CB_W0);
    const int oct = eb;
    float av[8];
#pragma unroll
    for (int i = 0; i < 8; i++) av[i] = b0s[oct * 8 + i];
#pragma unroll 8
    for (int e = 0; e < 64; e++) {
        float ce = ctxs[r * 65 + e];
#pragma unroll
        for (int i = 0; i < 8; i++) av[i] += ce * w0s[e * 64 + oct * 8 + i];
    }
    float4* op = (float4*)(out + (size_t)(b * SEQ + qt * 128 + row) * ED + oct * 8);
    op[0] = make_float4(av[0], av[1], av[2], av[3]);
    op[1] = make_float4(av[4], av[5], av[6], av[7]);
}

// ---------------------------------------------------------------------------
extern "C" void kernel_launch(void* const* d_in, const int* in_sizes, int n_in,
                              void* d_out, int out_size)
{
    const float* x  = (const float*)d_in[0];
    const float* Wk = (const float*)d_in[1];
    const float* bk = (const float*)d_in[2];
    const float* Wq = (const float*)d_in[3];
    const float* bq = (const float*)d_in[4];
    const float* Wv = (const float*)d_in[5];
    const float* bv = (const float*)d_in[6];
    const float* W0 = (const float*)d_in[7];
    const float* b0 = (const float*)d_in[8];
    float* out = (float*)d_out;

    cudaFuncSetAttribute(proj_kernel,    cudaFuncAttributeMaxDynamicSharedMemorySize, PJ_SMEM);
    cudaFuncSetAttribute(attn_partial,   cudaFuncAttributeMaxDynamicSharedMemorySize, AT_SMEM);
    cudaFuncSetAttribute(combine_kernel, cudaFuncAttributeMaxDynamicSharedMemorySize, CB_SMEM);

    prep_kernel<<<96, 256>>>(Wq, Wk, Wv);
    proj_kernel<<<dim3(128, 3), 256, PJ_SMEM>>>(x, bq, bk, bv);
    attn_partial<<<dim3(40, BATCH), 256, AT_SMEM>>>(out);
    combine_kernel<<<dim3(64, BATCH), 256, CB_SMEM>>>(W0, b0, out);
}

// round 8
// speedup vs baseline: 1.2360x; 1.2360x over previous
#include <cuda_runtime.h>
#include <cuda_bf16.h>
#include <cstdint>

#define BATCH 8
#define SEQ   2048
#define DM    1024
#define ED    64

// ---------------- device scratch (allocation-free rule) ----------------
__device__ __nv_bfloat16 g_qh[BATCH*SEQ*ED], g_ql[BATCH*SEQ*ED];
__device__ __nv_bfloat16 g_kh[BATCH*SEQ*ED], g_kl[BATCH*SEQ*ED];
__device__ __nv_bfloat16 g_vth[BATCH*ED*SEQ], g_vtl[BATCH*ED*SEQ];   // V transposed [b][e][t]
__device__ __nv_bfloat16 g_wth[3*ED*DM],  g_wtl[3*ED*DM];            // W^T [mat][n][d]
// split-K partials: [b][qt][chunk][128][64] fp32 + per-row m/l
__device__ float g_pctx[BATCH*16*4*128*64];
__device__ float g_pm[BATCH*16*4*128];
__device__ float g_pl[BATCH*16*4*128];

// unit table: (qt<<2)|chunk, sorted by chunk size descending (8,6,4,2 tiles)
__constant__ uint8_t c_units[40] = {
    (3<<2)|0,(4<<2)|0,(5<<2)|0,(6<<2)|0,(7<<2)|0,(7<<2)|1,(8<<2)|0,(8<<2)|1,
    (9<<2)|0,(9<<2)|1,(10<<2)|0,(10<<2)|1,(11<<2)|0,(11<<2)|1,(11<<2)|2,
    (12<<2)|0,(12<<2)|1,(12<<2)|2,(13<<2)|0,(13<<2)|1,(13<<2)|2,
    (14<<2)|0,(14<<2)|1,(14<<2)|2,(15<<2)|0,(15<<2)|1,(15<<2)|2,(15<<2)|3,
    (2<<2)|0,(6<<2)|1,(10<<2)|2,(14<<2)|3,
    (1<<2)|0,(5<<2)|1,(9<<2)|2,(13<<2)|3,
    (0<<2)|0,(4<<2)|1,(8<<2)|2,(12<<2)|3
};

// ---------------- helpers ----------------
__device__ __forceinline__ uint32_t smem_u32(const void* p) {
    uint32_t a;
    asm("{ .reg .u64 t; cvta.to.shared.u64 t, %1; cvt.u32.u64 %0, t; }" : "=r"(a) : "l"(p));
    return a;
}
__device__ __forceinline__ void ldmA(uint32_t* a, uint32_t addr) {
    asm volatile("ldmatrix.sync.aligned.m8n8.x4.shared.b16 {%0,%1,%2,%3}, [%4];"
        : "=r"(a[0]), "=r"(a[1]), "=r"(a[2]), "=r"(a[3]) : "r"(addr));
}
// x4 B-load: two adjacent n-tiles (ni, ni+1), each {k-lo, k-hi}.
// b[0],b[1] -> ni ; b[2],b[3] -> ni+1
__device__ __forceinline__ void ldmB4(uint32_t* b, uint32_t addr) {
    asm volatile("ldmatrix.sync.aligned.m8n8.x4.shared.b16 {%0,%1,%2,%3}, [%4];"
        : "=r"(b[0]), "=r"(b[1]), "=r"(b[2]), "=r"(b[3]) : "r"(addr));
}
__device__ __forceinline__ void mmaf(float* d, const uint32_t* a, const uint32_t* b) {
    asm volatile("mma.sync.aligned.m16n8k16.row.col.f32.bf16.bf16.f32 "
        "{%0,%1,%2,%3}, {%4,%5,%6,%7}, {%8,%9}, {%0,%1,%2,%3};"
        : "+f"(d[0]), "+f"(d[1]), "+f"(d[2]), "+f"(d[3])
        : "r"(a[0]), "r"(a[1]), "r"(a[2]), "r"(a[3]), "r"(b[0]), "r"(b[1]));
}
#define CP16(dst, src)  asm volatile("cp.async.cg.shared.global [%0], [%1], 16;" :: "r"(dst), "l"(src) : "memory")
#define CP_COMMIT()     asm volatile("cp.async.commit_group;" ::: "memory")
#define CP_WAIT0()      asm volatile("cp.async.wait_group 0;" ::: "memory")
#define CP_WAIT1()      asm volatile("cp.async.wait_group 1;" ::: "memory")

union U4 { uint4 u; __nv_bfloat16 h[8]; };
union U2 { uint2 u; __nv_bfloat16 h[4]; };
union UB2 { uint32_t u; __nv_bfloat16 h[2]; };

__device__ __forceinline__ void split2(float f, __nv_bfloat16& hi, __nv_bfloat16& lo) {
    hi = __float2bfloat16(f);
    lo = __float2bfloat16(f - __bfloat162float(hi));
}
__device__ __forceinline__ uint32_t packbf(__nv_bfloat16 a, __nv_bfloat16 b) {
    UB2 u; u.h[0] = a; u.h[1] = b; return u.u;
}

// ---------------------------------------------------------------------------
// Kernel 0: weights -> transposed bf16 hi/lo.
// ---------------------------------------------------------------------------
__global__ void prep_kernel(const float* __restrict__ Wq, const float* __restrict__ Wk,
                            const float* __restrict__ Wv)
{
    int tid = blockIdx.x * 256 + threadIdx.x;
    for (int i = tid; i < 3 * ED * DM; i += 96 * 256) {
        int mat = i >> 16, rem = i & 65535;
        int n = rem >> 10, d = rem & 1023;
        const float* W = (mat == 0) ? Wq : (mat == 1) ? Wk : Wv;
        __nv_bfloat16 h, l;
        split2(W[d * ED + n], h, l);
        g_wth[i] = h; g_wtl[i] = l;
    }
}

// ---------------------------------------------------------------------------
// Kernel 1: QKV projection via mma.sync bf16x3 (W staged via cp.async).
// grid (128, 3) x 256 thr; launch_bounds(256,2) for 2-CTA occupancy.
// ---------------------------------------------------------------------------
#define PJ_XH 512
#define PJ_XL 18944
#define PJ_WH 37376
#define PJ_WL 46592
#define PJ_SMEM 55808

__global__ void __launch_bounds__(256, 2)
proj_kernel(const float* __restrict__ x, const float* __restrict__ bq,
            const float* __restrict__ bk, const float* __restrict__ bv)
{
    extern __shared__ char smem[];
    const uint32_t sb = smem_u32(smem);
    const int tid = threadIdx.x, lane = tid & 31, wid = tid >> 5;
    const int mw = wid >> 1, nh = wid & 1;
    const int g = lane >> 2, tq = lane & 3;
    const int mat = blockIdx.y;
    const int rowbase = blockIdx.x * 128;
    const float* bias = (mat == 0) ? bq : (mat == 1) ? bk : bv;
    if (tid < 64) ((float*)smem)[tid] = bias[tid];

    const __nv_bfloat16* wh = g_wth + (size_t)mat * ED * DM;
    const __nv_bfloat16* wl = g_wtl + (size_t)mat * ED * DM;

    float acc[2][4][4];
#pragma unroll
    for (int a = 0; a < 2; a++)
#pragma unroll
        for (int bb = 0; bb < 4; bb++)
#pragma unroll
            for (int c = 0; c < 4; c++) acc[a][bb][c] = 0.0f;

    for (int k0 = 0; k0 < DM; k0 += 64) {
        __syncthreads();
        // W tiles via cp.async, issued first so they overlap X conversion
#pragma unroll
        for (int i = 0; i < 4; i++) {
            int idx = i * 256 + tid;
            int part = idx >> 9, rem = idx & 511;
            int r = rem >> 3, jj = rem & 7;
            const __nv_bfloat16* src = (part ? wl : wh) + (size_t)r * DM + k0;
            CP16(sb + (part ? PJ_WL : PJ_WH) + r * 144 + jj * 16, (const char*)src + jj * 16);
        }
        CP_COMMIT();
#pragma unroll
        for (int i = 0; i < 8; i++) {                    // X tile 128x64 fp32 -> hi/lo
            int idx = i * 256 + tid;
            int r = idx >> 4, jj = idx & 15;
            float4 v = __ldg((const float4*)(x + (size_t)(rowbase + r) * DM + k0) + jj);
            U2 h, l;
            split2(v.x, h.h[0], l.h[0]); split2(v.y, h.h[1], l.h[1]);
            split2(v.z, h.h[2], l.h[2]); split2(v.w, h.h[3], l.h[3]);
            *(uint2*)(smem + PJ_XH + r * 144 + jj * 8) = h.u;
            *(uint2*)(smem + PJ_XL + r * 144 + jj * 8) = l.u;
        }
        CP_WAIT0();
        __syncthreads();

#pragma unroll
        for (int kc = 0; kc < 4; kc++) {
            uint32_t ah[2][4], al[2][4];
#pragma unroll
            for (int mi = 0; mi < 2; mi++) {
                uint32_t ao = (uint32_t)(mw * 32 + mi * 16 + (lane & 15)) * 144 + kc * 32 + (lane >> 4) * 16;
                ldmA(ah[mi], sb + PJ_XH + ao);
                ldmA(al[mi], sb + PJ_XL + ao);
            }
#pragma unroll
            for (int nip = 0; nip < 2; nip++) {          // ni = 2*nip, 2*nip+1
                uint32_t bo = (uint32_t)(nh * 32 + (nip * 2 + (lane >> 4)) * 8 + (lane & 7)) * 144
                            + kc * 32 + ((lane >> 3) & 1) * 16;
                uint32_t bh[4], bl[4];
                ldmB4(bh, sb + PJ_WH + bo);
                ldmB4(bl, sb + PJ_WL + bo);
#pragma unroll
                for (int mi = 0; mi < 2; mi++) {
                    mmaf(acc[mi][2 * nip],     ah[mi], bh);
                    mmaf(acc[mi][2 * nip],     ah[mi], bl);
                    mmaf(acc[mi][2 * nip],     al[mi], bh);
                    mmaf(acc[mi][2 * nip + 1], ah[mi], bh + 2);
                    mmaf(acc[mi][2 * nip + 1], ah[mi], bl + 2);
                    mmaf(acc[mi][2 * nip + 1], al[mi], bh + 2);
                }
            }
        }
    }

    // epilogue: fragments -> staged smem [128][65] -> coalesced hi/lo global stores
    __syncthreads();
    const float scale = (mat == 0) ? 0.125f : 1.0f;
    const float* bs = (const float*)smem;
    float* stg = (float*)(smem + 512);
#pragma unroll
    for (int mi = 0; mi < 2; mi++)
#pragma unroll
        for (int ni = 0; ni < 4; ni++)
#pragma unroll
            for (int j = 0; j < 4; j++) {
                int row = mw * 32 + mi * 16 + (j >> 1) * 8 + g;
                int col = nh * 32 + ni * 8 + tq * 2 + (j & 1);
                stg[row * 65 + col] = (acc[mi][ni][j] + bs[col]) * scale;
            }
    __syncthreads();

    if (mat < 2) {
        int r = tid >> 1, half = tid & 1;
        U4 hb[4], lb[4];
#pragma unroll
        for (int i = 0; i < 32; i++)
            split2(stg[r * 65 + half * 32 + i], hb[i >> 3].h[i & 7], lb[i >> 3].h[i & 7]);
        __nv_bfloat16* dh = ((mat == 0) ? g_qh : g_kh) + (size_t)(rowbase + r) * ED + half * 32;
        __nv_bfloat16* dl = ((mat == 0) ? g_ql : g_kl) + (size_t)(rowbase + r) * ED + half * 32;
#pragma unroll
        for (int i = 0; i < 4; i++) { ((uint4*)dh)[i] = hb[i].u; ((uint4*)dl)[i] = lb[i].u; }
    } else {
        int e = tid >> 2, qq = tid & 3;
        int b = rowbase >> 11, tb = (rowbase & 2047) + qq * 32;
        U4 hb[4], lb[4];
#pragma unroll
        for (int i = 0; i < 32; i++)
            split2(stg[(qq * 32 + i) * 65 + e], hb[i >> 3].h[i & 7], lb[i >> 3].h[i & 7]);
        __nv_bfloat16* dh = g_vth + (size_t)(b * ED + e) * SEQ + tb;
        __nv_bfloat16* dl = g_vtl + (size_t)(b * ED + e) * SEQ + tb;
#pragma unroll
        for (int i = 0; i < 4; i++) { ((uint4*)dh)[i] = hb[i].u; ((uint4*)dl)[i] = lb[i].u; }
    }
}

// ---------------------------------------------------------------------------
// Kernel 2: split-K causal flash attention partials.
// 8 warps x 16 rows x full N=64 -> softmax is warp-local (shuffle only).
// grid (40, 8) x 256 thr. cp.async double-buffered K/V stages. x4 B-loads.
// ---------------------------------------------------------------------------
#define AT_QH   2048
#define AT_QL   20480
#define AT_ST   38912
#define AT_STG  36864
#define AT_CTXB 2048
#define AT_SMEM 112640

__global__ void __launch_bounds__(256, 1)
attn_partial(float* __restrict__ dummy)
{
    extern __shared__ char smem[];
    const uint32_t sb = smem_u32(smem);
    const int tid = threadIdx.x, lane = tid & 31, wid = tid >> 5;
    const int g = lane >> 2, tq = lane & 3;
    const int b = blockIdx.y;
    const uint32_t u = c_units[blockIdx.x];
    const int qt = u >> 2, ck = u & 3;
    const int qb = qt * 128;
    const int t0 = ck * 8;
    const int t1 = min(t0 + 8, 2 * qt + 2);

    // Q tile hi/lo via cp.async (group 0)
#pragma unroll
    for (int i = 0; i < 8; i++) {
        int idx = i * 256 + tid;
        int part = idx >> 10, rem = idx & 1023;
        int r = rem >> 3, jj = rem & 7;
        const __nv_bfloat16* src = (part ? g_ql : g_qh) + (size_t)(b * SEQ + qb + r) * ED;
        CP16(sb + (part ? AT_QL : AT_QH) + r * 144 + jj * 16, (const char*)src + jj * 16);
    }
    CP_COMMIT();

    auto stage_tile = [&](int t, int sg) {
        uint32_t base = sb + AT_ST + sg * AT_STG;
#pragma unroll
        for (int i = 0; i < 8; i++) {
            int idx = i * 256 + tid;
            int part = idx >> 9, rem = idx & 511;
            int r = rem >> 3, jj = rem & 7;
            const __nv_bfloat16* src;
            if (part == 0)      src = g_kh  + (size_t)(b * SEQ + t * 64 + r) * ED;
            else if (part == 1) src = g_kl  + (size_t)(b * SEQ + t * 64 + r) * ED;
            else if (part == 2) src = g_vth + (size_t)(b * ED + r) * SEQ + t * 64;
            else                src = g_vtl + (size_t)(b * ED + r) * SEQ + t * 64;
            CP16(base + part * 9216 + r * 144 + jj * 16, (const char*)src + jj * 16);
        }
    };
    stage_tile(t0, 0);
    CP_COMMIT();

    float ctx[8][4];
#pragma unroll
    for (int bb = 0; bb < 8; bb++)
#pragma unroll
        for (int c = 0; c < 4; c++) ctx[bb][c] = 0.0f;
    float mrow[2] = {-1e30f, -1e30f};
    float lrow[2] = {0.0f, 0.0f};

    for (int t = t0; t < t1; t++) {
        const int cur = (t - t0) & 1;
        __syncthreads();             // all warps done reading stage cur^1 (iter t-1)
        if (t + 1 < t1) { stage_tile(t + 1, cur ^ 1); CP_COMMIT(); CP_WAIT1(); }
        else            { CP_WAIT0(); }
        __syncthreads();             // stage cur visible to all warps
        const uint32_t kb = sb + AT_ST + cur * AT_STG;

        // S = Q K^T : warp's 16 rows x full 64 keys
        float s[8][4];
#pragma unroll
        for (int bb = 0; bb < 8; bb++)
#pragma unroll
            for (int c = 0; c < 4; c++) s[bb][c] = 0.0f;

#pragma unroll
        for (int kc = 0; kc < 4; kc++) {
            uint32_t ah[4], al[4];
            uint32_t ao = (uint32_t)(wid * 16 + (lane & 15)) * 144 + kc * 32 + (lane >> 4) * 16;
            ldmA(ah, sb + AT_QH + ao);
            ldmA(al, sb + AT_QL + ao);
#pragma unroll
            for (int nip = 0; nip < 4; nip++) {          // ni = 2*nip, 2*nip+1
                uint32_t bo = (uint32_t)((nip * 2 + (lane >> 4)) * 8 + (lane & 7)) * 144
                            + kc * 32 + ((lane >> 3) & 1) * 16;
                uint32_t bh[4], bl[4];
                ldmB4(bh, kb + bo);
                ldmB4(bl, kb + 9216 + bo);
                mmaf(s[2 * nip],     ah, bh);
                mmaf(s[2 * nip],     ah, bl);
                mmaf(s[2 * nip],     al, bh);
                mmaf(s[2 * nip + 1], ah, bh + 2);
                mmaf(s[2 * nip + 1], ah, bl + 2);
                mmaf(s[2 * nip + 1], al, bh + 2);
            }
        }

        if (t >= 2 * qt) {                               // causal mask (diagonal tiles)
#pragma unroll
            for (int ni = 0; ni < 8; ni++)
#pragma unroll
                for (int j = 0; j < 4; j++) {
                    int row = qb + wid * 16 + (j >> 1) * 8 + g;
                    int col = t * 64 + ni * 8 + tq * 2 + (j & 1);
                    if (col > row) s[ni][j] = -1e30f;
                }
        }

        // warp-local online softmax (quad shuffle only)
        float corr[2];
#pragma unroll
        for (int rh = 0; rh < 2; rh++) {
            float mx = -1e30f;
#pragma unroll
            for (int ni = 0; ni < 8; ni++)
                mx = fmaxf(mx, fmaxf(s[ni][rh * 2], s[ni][rh * 2 + 1]));
            mx = fmaxf(mx, __shfl_xor_sync(0xffffffffu, mx, 1));
            mx = fmaxf(mx, __shfl_xor_sync(0xffffffffu, mx, 2));
            float nm = fmaxf(mrow[rh], mx);
            corr[rh] = __expf(mrow[rh] - nm);
            mrow[rh] = nm;
            float sum = 0.0f;
#pragma unroll
            for (int ni = 0; ni < 8; ni++) {
                float p0 = __expf(s[ni][rh * 2] - nm);
                float p1 = __expf(s[ni][rh * 2 + 1] - nm);
                s[ni][rh * 2] = p0; s[ni][rh * 2 + 1] = p1;
                sum += p0 + p1;
            }
            sum += __shfl_xor_sync(0xffffffffu, sum, 1);
            sum += __shfl_xor_sync(0xffffffffu, sum, 2);
            lrow[rh] = lrow[rh] * corr[rh] + sum;
        }
#pragma unroll
        for (int ni = 0; ni < 8; ni++)
#pragma unroll
            for (int j = 0; j < 4; j++) ctx[ni][j] *= corr[j >> 1];

        // PV: P (regs, hi/lo A-frags) @ V^T (smem B-frags via x4)
#pragma unroll
        for (int kc = 0; kc < 4; kc++) {
            uint32_t ph[4], pl[4];
            {
                __nv_bfloat16 h0, l0, h1, l1;
                split2(s[2 * kc][0], h0, l0);     split2(s[2 * kc][1], h1, l1);
                ph[0] = packbf(h0, h1);           pl[0] = packbf(l0, l1);
                split2(s[2 * kc][2], h0, l0);     split2(s[2 * kc][3], h1, l1);
                ph[1] = packbf(h0, h1);           pl[1] = packbf(l0, l1);
                split2(s[2 * kc + 1][0], h0, l0); split2(s[2 * kc + 1][1], h1, l1);
                ph[2] = packbf(h0, h1);           pl[2] = packbf(l0, l1);
                split2(s[2 * kc + 1][2], h0, l0); split2(s[2 * kc + 1][3], h1, l1);
                ph[3] = packbf(h0, h1);           pl[3] = packbf(l0, l1);
            }
#pragma unroll
            for (int nip = 0; nip < 4; nip++) {          // ni = 2*nip, 2*nip+1
                uint32_t bo = (uint32_t)((nip * 2 + (lane >> 4)) * 8 + (lane & 7)) * 144
                            + kc * 32 + ((lane >> 3) & 1) * 16;
                uint32_t bh[4], bl[4];
                ldmB4(bh, kb + 18432 + bo);
                ldmB4(bl, kb + 27648 + bo);
                mmaf(ctx[2 * nip],     ph, bh);
                mmaf(ctx[2 * nip],     ph, bl);
                mmaf(ctx[2 * nip],     pl, bh);
                mmaf(ctx[2 * nip + 1], ph, bh + 2);
                mmaf(ctx[2 * nip + 1], ph, bl + 2);
                mmaf(ctx[2 * nip + 1], pl, bh + 2);
            }
        }
    }

    // ---- write partials (unnormalized ctx + m/l) ----
    __syncthreads();                 // Q area dead; safe to reuse as ctxb
    float* ctxb = (float*)(smem + AT_CTXB);    // stride 68 floats
#pragma unroll
    for (int ni = 0; ni < 8; ni++)
#pragma unroll
        for (int j = 0; j < 4; j++) {
            int row = wid * 16 + (j >> 1) * 8 + g;
            int col = ni * 8 + tq * 2 + (j & 1);
            ctxb[row * 68 + col] = ctx[ni][j];
        }
    if (tq == 0) {
        size_t mlb = (size_t)((b * 16 + qt) * 4 + ck) * 128;
#pragma unroll
        for (int rh = 0; rh < 2; rh++) {
            int row = wid * 16 + rh * 8 + g;
            g_pm[mlb + row] = mrow[rh];
            g_pl[mlb + row] = lrow[rh];
        }
    }
    __syncthreads();

    const int r = tid >> 1, half = tid & 1;
    float* dst = g_pctx + ((size_t)((b * 16 + qt) * 4 + ck) << 13) + r * 64 + half * 32;
    const float4* srcf = (const float4*)(ctxb + r * 68 + half * 32);
#pragma unroll
    for (int i = 0; i < 8; i++) ((float4*)dst)[i] = srcf[i];
    (void)dummy;
}

// ---------------------------------------------------------------------------
// Kernel 3: combine partials + output projection. grid (16, 8) x 256 thr.
// Each CTA: 128 rows. Register-tiled 4x8 epilogue (minimal LDS traffic).
// SMEM: ctxs[128][65]f32 @0, W0 @33280, b0 @49664. 49920 B.
// ---------------------------------------------------------------------------
#define CB_W0 33280
#define CB_B0 49664
#define CB_SMEM 49920

__global__ void __launch_bounds__(256, 1)
combine_kernel(const float* __restrict__ W0, const float* __restrict__ b0,
               float* __restrict__ out)
{
    extern __shared__ char smem[];
    const int tid = threadIdx.x;
    const int qt = blockIdx.x, b = blockIdx.y;
    const int nchunks = (qt >> 2) + 1;

    float* w0s  = (float*)(smem + CB_W0);
    float* b0s  = (float*)(smem + CB_B0);
    float* ctxs = (float*)smem;                // stride 65 floats

#pragma unroll
    for (int i = 0; i < 4; i++)
        ((float4*)w0s)[i * 256 + tid] = __ldg((const float4*)W0 + i * 256 + tid);
    if (tid < 64) b0s[tid] = b0[tid];

    // merge chunk partials: 2 threads per row (128 rows/CTA), coalesced float4
    const int r = tid >> 1, half = tid & 1;
    const size_t base = (size_t)((b * 16 + qt) * 4);
    float mc[4], lc[4];
#pragma unroll
    for (int c = 0; c < 4; c++) {
        if (c < nchunks) {
            mc[c] = g_pm[(base + c) * 128 + r];
            lc[c] = g_pl[(base + c) * 128 + r];
        } else { mc[c] = -1e30f; lc[c] = 0.0f; }
    }
    float ms = fmaxf(fmaxf(mc[0], mc[1]), fmaxf(mc[2], mc[3]));
    float ls = 0.0f, wsc[4];
#pragma unroll
    for (int c = 0; c < 4; c++) { wsc[c] = __expf(mc[c] - ms); ls += lc[c] * wsc[c]; }
    const float inv = 1.0f / ls;

    float acc[32];
#pragma unroll
    for (int i = 0; i < 32; i++) acc[i] = 0.0f;
#pragma unroll
    for (int c = 0; c < 4; c++) {
        if (c < nchunks) {
            const float4* p = (const float4*)(g_pctx + ((base + c) << 13) + r * 64 + half * 32);
            float w = wsc[c];
#pragma unroll
            for (int i = 0; i < 8; i++) {
                float4 v = p[i];
                acc[4 * i + 0] += v.x * w; acc[4 * i + 1] += v.y * w;
                acc[4 * i + 2] += v.z * w; acc[4 * i + 3] += v.w * w;
            }
        }
    }
#pragma unroll
    for (int i = 0; i < 32; i++) ctxs[r * 65 + half * 32 + i] = acc[i] * inv;
    __syncthreads();

    // output: each thread computes 4 rows x 8 cols of out = ctx @ W0 + b0
    const int ro = tid >> 3, co = tid & 7;     // ro 0..31 -> rows ro*4+k ; co 0..7
    float av[4][8];
#pragma unroll
    for (int k = 0; k < 4; k++)
#pragma unroll
        for (int i = 0; i < 8; i++) av[k][i] = b0s[co * 8 + i];

#pragma unroll 8
    for (int e = 0; e < 64; e++) {
        const float4* wp = (const float4*)(w0s + e * 64 + co * 8);
        float4 wa = wp[0], wb = wp[1];
#pragma unroll
        for (int k = 0; k < 4; k++) {
            float ce = ctxs[(ro * 4 + k) * 65 + e];
            av[k][0] += ce * wa.x; av[k][1] += ce * wa.y;
            av[k][2] += ce * wa.z; av[k][3] += ce * wa.w;
            av[k][4] += ce * wb.x; av[k][5] += ce * wb.y;
            av[k][6] += ce * wb.z; av[k][7] += ce * wb.w;
        }
    }
#pragma unroll
    for (int k = 0; k < 4; k++) {
        float4* op = (float4*)(out + (size_t)(b * SEQ + qt * 128 + ro * 4 + k) * ED + co * 8);
        op[0] = make_float4(av[k][0], av[k][1], av[k][2], av[k][3]);
        op[1] = make_float4(av[k][4], av[k][5], av[k][6], av[k][7]);
    }
}

// ---------------------------------------------------------------------------
extern "C" void kernel_launch(void* const* d_in, const int* in_sizes, int n_in,
                              void* d_out, int out_size)
{
    const float* x  = (const float*)d_in[0];
    const float* Wk = (const float*)d_in[1];
    const float* bk = (const float*)d_in[2];
    const float* Wq = (const float*)d_in[3];
    const float* bq = (const float*)d_in[4];
    const float* Wv = (const float*)d_in[5];
    const float* bv = (const float*)d_in[6];
    const float* W0 = (const float*)d_in[7];
    const float* b0 = (const float*)d_in[8];
    float* out = (float*)d_out;

    cudaFuncSetAttribute(proj_kernel,    cudaFuncAttributeMaxDynamicSharedMemorySize, PJ_SMEM);
    cudaFuncSetAttribute(attn_partial,   cudaFuncAttributeMaxDynamicSharedMemorySize, AT_SMEM);
    cudaFuncSetAttribute(combine_kernel, cudaFuncAttributeMaxDynamicSharedMemorySize, CB_SMEM);

    prep_kernel<<<96, 256>>>(Wq, Wk, Wv);
    proj_kernel<<<dim3(128, 3), 256, PJ_SMEM>>>(x, bq, bk, bv);
    attn_partial<<<dim3(40, BATCH), 256, AT_SMEM>>>(out);
    combine_kernel<<<dim3(16, BATCH), 256, CB_SMEM>>>(W0, b0, out);
}